// round 7
// baseline (speedup 1.0000x reference)
#include <cuda_runtime.h>
#include <cuda_bf16.h>
#include <cstdint>

typedef unsigned long long u64;

constexpr int Bc = 2;
constexpr int Lc = 4096;
constexpr int DK = 128;
constexpr int DV = 128;
constexpr int C  = 64;
constexpr int NC = Lc / C;       // 64
constexpr int TC = Bc * NC;      // 128
constexpr float EPS = 1e-6f;

constexpr int PK = 130;          // k-contiguous row stride (Q, K in k3)
constexpr int PJ = 66;           // j-contiguous row stride (A in k3)

// Scratch: g_kv / g_kvpre stored [bc][k][v]  (v contiguous)
__device__ float g_kv   [(size_t)TC * DK * DV];
__device__ float g_kvpre[(size_t)TC * DK * DV];
__device__ float g_ks   [(size_t)TC * DK];
__device__ float g_kspre[(size_t)TC * DK];

__device__ __forceinline__ float phi(float x) {
    return x > 0.f ? x + 1.f : __expf(x);
}
__device__ __forceinline__ void fma2(u64& d, u64 a, u64 b) {
    asm("fma.rn.f32x2 %0, %1, %2, %0;" : "+l"(d) : "l"(a), "l"(b));
}
__device__ __forceinline__ float2 up2(u64 v) {
    float2 f; asm("mov.b64 {%0, %1}, %2;" : "=f"(f.x), "=f"(f.y) : "l"(v)); return f;
}
__device__ __forceinline__ u64 pk(float lo, float hi) {
    u64 r; asm("mov.b64 %0, {%1, %2};" : "=l"(r) : "f"(lo), "f"(hi)); return r;
}
__device__ __forceinline__ u64 dup2(float x) {
    u64 r; asm("mov.b64 %0, {%1, %1};" : "=l"(r) : "f"(x)); return r;
}
__device__ __forceinline__ u64 lds64(const float* p) {
    return *reinterpret_cast<const u64*>(p);
}

// ---------------------------------------------------------------------------
// Kernel 1: KV[k][v] = sum_l phiK[l][k] V[l][v]  -> g_kv[bc][k][v]
// grid = 2*TC (chunk x k-half), 512 threads, 2 CTAs/SM (48KB static smem).
// No transposes. Mixed FMA2/FFMA (dual-pipe). Coalesced STG.128 output.
// ---------------------------------------------------------------------------
__global__ void __launch_bounds__(512, 2)
k_chunk_kv(const float* __restrict__ K, const float* __restrict__ V) {
    __shared__ float sKh[C * 64];    // 16 KB: phiK k-half, row-major
    __shared__ float sV [C * DV];    // 32 KB: V full, row-major

    const int bc = blockIdx.x >> 1;
    const int kh = (blockIdx.x & 1) * 64;
    const int b  = bc / NC;
    const int c  = bc % NC;
    const int l0 = c * C;
    const int tid = threadIdx.x;

    // stage phiK half: coalesced LDG.128 -> conflict-free STS.128
    for (int e = tid; e < 1024; e += 512) {
        const int l = e >> 4, k4 = (e & 15) * 4;
        float4 x = *(const float4*)&K[((size_t)(b * Lc + l0 + l)) * DK + kh + k4];
        *(float4*)&sKh[l * 64 + k4] = make_float4(phi(x.x), phi(x.y), phi(x.z), phi(x.w));
    }
    // stage V full: coalesced LDG.128 -> conflict-free STS.128
    for (int e = tid; e < 2048; e += 512) {
        const int l = e >> 5, v4 = (e & 31) * 4;
        float4 x = *(const float4*)&V[((size_t)(b * Lc + l0 + l)) * DV + v4];
        *(float4*)&sV[l * DV + v4] = x;
    }
    __syncthreads();

    const int w = tid >> 5, tx = tid & 31;
    const int half = tx >> 4, txl = tx & 15;
    const int k0 = (w * 2 + half) * 2;    // 2 consecutive local k per thread
    const int v0 = txl * 8;               // 8 consecutive v per thread

    u64   a2[2][2];   // FMA2 accs: [dk][vp] -> (v0, v0+1), (v0+2, v0+3)
    float as[2][4];   // scalar accs: v0+4 .. v0+7
#pragma unroll
    for (int r = 0; r < 2; r++) {
        a2[r][0] = a2[r][1] = 0ull;
#pragma unroll
        for (int s = 0; s < 4; s++) as[r][s] = 0.f;
    }

#pragma unroll 4
    for (int l = 0; l < C; l++) {
        const float a0 = sKh[l * 64 + k0];
        const float a1 = sKh[l * 64 + k0 + 1];
        const u64 d0 = dup2(a0), d1 = dup2(a1);
        const ulonglong2 P = *(const ulonglong2*)&sV[l * DV + v0];      // v0..v0+3 as 2 pairs
        const float4     F = *(const float4*)    &sV[l * DV + v0 + 4];  // v0+4..v0+7 scalars
        fma2(a2[0][0], d0, P.x); fma2(a2[0][1], d0, P.y);
        fma2(a2[1][0], d1, P.x); fma2(a2[1][1], d1, P.y);
        as[0][0] = fmaf(a0, F.x, as[0][0]); as[0][1] = fmaf(a0, F.y, as[0][1]);
        as[0][2] = fmaf(a0, F.z, as[0][2]); as[0][3] = fmaf(a0, F.w, as[0][3]);
        as[1][0] = fmaf(a1, F.x, as[1][0]); as[1][1] = fmaf(a1, F.y, as[1][1]);
        as[1][2] = fmaf(a1, F.z, as[1][2]); as[1][3] = fmaf(a1, F.w, as[1][3]);
    }

    // store [bc][k][v]: per dk two coalesced float4
    float* kvout = g_kv + (size_t)bc * DK * DV;
#pragma unroll
    for (int r = 0; r < 2; r++) {
        const int kg = kh + k0 + r;
        float2 p0 = up2(a2[r][0]), p1 = up2(a2[r][1]);
        *(float4*)&kvout[(size_t)kg * DV + v0]     = make_float4(p0.x, p0.y, p1.x, p1.y);
        *(float4*)&kvout[(size_t)kg * DV + v0 + 4] = make_float4(as[r][0], as[r][1], as[r][2], as[r][3]);
    }

    // per-chunk phiK column sums for this k-half
    if (tid < 64) {
        float s = 0.f;
#pragma unroll 8
        for (int l = 0; l < C; l++) s += sKh[l * 64 + tid];
        g_ks[(size_t)bc * DK + kh + tid] = s;
    }
}

// ---------------------------------------------------------------------------
// Kernel 2: exclusive prefix over chunks, coalesced serial (unroll-4 MLP)
// grid = 17 x 512: CTAs 0-15 do kv rows (b,k) x lanes v; CTA 16 does ks
// ---------------------------------------------------------------------------
__global__ void __launch_bounds__(512, 2)
k_scan(void) {
    if (blockIdx.x < 16) {
        const int t   = blockIdx.x * 512 + threadIdx.x;  // 0..8191
        const int row = t >> 5;                          // (b,k): 0..255
        const int v4  = (t & 31) * 4;
        const size_t cstr = (size_t)DK * DV;
        const int b = row >> 7, k = row & 127;
        const size_t base = (size_t)(b * NC) * cstr + (size_t)k * DV + v4;

        float4 run = make_float4(0.f, 0.f, 0.f, 0.f);
#pragma unroll 1
        for (int c = 0; c < NC; c += 4) {
            float4 x0 = *(const float4*)(g_kv + base + (size_t)(c + 0) * cstr);
            float4 x1 = *(const float4*)(g_kv + base + (size_t)(c + 1) * cstr);
            float4 x2 = *(const float4*)(g_kv + base + (size_t)(c + 2) * cstr);
            float4 x3 = *(const float4*)(g_kv + base + (size_t)(c + 3) * cstr);
            *(float4*)(g_kvpre + base + (size_t)(c + 0) * cstr) = run;
            run.x += x0.x; run.y += x0.y; run.z += x0.z; run.w += x0.w;
            *(float4*)(g_kvpre + base + (size_t)(c + 1) * cstr) = run;
            run.x += x1.x; run.y += x1.y; run.z += x1.z; run.w += x1.w;
            *(float4*)(g_kvpre + base + (size_t)(c + 2) * cstr) = run;
            run.x += x2.x; run.y += x2.y; run.z += x2.z; run.w += x2.w;
            *(float4*)(g_kvpre + base + (size_t)(c + 3) * cstr) = run;
            run.x += x3.x; run.y += x3.y; run.z += x3.z; run.w += x3.w;
        }
    } else if (threadIdx.x < 64) {
        const int b  = threadIdx.x >> 5;
        const int k4 = (threadIdx.x & 31) * 4;
        const size_t base = (size_t)(b * NC) * DK + k4;
        float4 run = make_float4(0.f, 0.f, 0.f, 0.f);
#pragma unroll 4
        for (int c = 0; c < NC; c++) {
            float4 x = *(const float4*)(g_ks + base + (size_t)c * DK);
            *(float4*)(g_kspre + base + (size_t)c * DK) = run;
            run.x += x.x; run.y += x.y; run.z += x.z; run.w += x.w;
        }
    }
}

// ---------------------------------------------------------------------------
// Kernel 3: A = mask(phiQ phiK^T); out = (A V + phiQ Spre) / Z
// grid = TC, 512 threads, 1 CTA/SM, smem ~117 KB. V row-major (no transpose),
// Spre read from L1/L2 in-loop, phase 2 v-packed mixed FMA.
// ---------------------------------------------------------------------------
__global__ void __launch_bounds__(512, 1)
k_output(const float* __restrict__ Q, const float* __restrict__ K,
         const float* __restrict__ V, float* __restrict__ out) {
    extern __shared__ float sm[];
    float* sQ  = sm;                        // [64][PK] phiQ row-major
    float* sK  = sQ  + C * PK;              // [64][PK] phiK row-major
    float* sA  = sK  + C * PK;              // [64][PJ] A row-major
    float* sV  = sA  + C * PJ;              // [64][128] V row-major
    float* sKs = sV  + C * DV;              // [128]
    float* sZ  = sKs + DK;                  // [64]

    const int bc = blockIdx.x;
    const int b  = bc / NC;
    const int c  = bc % NC;
    const int l0 = c * C;
    const int tid = threadIdx.x;

    // Q, K with phi: LDG.128 -> 2x STS.64 (PK=130 keeps lds64 conflict-free)
    for (int e = tid; e < 2048; e += 512) {
        const int l = e >> 5, k4 = (e & 31) * 4;
        const size_t g = ((size_t)(b * Lc + l0 + l)) * DK + k4;
        float4 q = *(const float4*)&Q[g];
        float4 k = *(const float4*)&K[g];
        *(float2*)&sQ[l * PK + k4]     = make_float2(phi(q.x), phi(q.y));
        *(float2*)&sQ[l * PK + k4 + 2] = make_float2(phi(q.z), phi(q.w));
        *(float2*)&sK[l * PK + k4]     = make_float2(phi(k.x), phi(k.y));
        *(float2*)&sK[l * PK + k4 + 2] = make_float2(phi(k.z), phi(k.w));
    }
    // V row-major: LDG.128 -> STS.128, conflict-free
    for (int e = tid; e < 2048; e += 512) {
        const int l = e >> 5, v4 = (e & 31) * 4;
        float4 x = *(const float4*)&V[((size_t)(b * Lc + l0 + l)) * DV + v4];
        *(float4*)&sV[l * DV + v4] = x;
    }
    if (tid < DK) sKs[tid] = g_kspre[(size_t)bc * DK + tid];
    if (tid < C)  sZ[tid] = 0.f;
    __syncthreads();

    const int w = tid >> 5, tx = tid & 31;
    const int half = tx >> 4, txl = tx & 15;

    // ---- phase 1: A[i][j] (pair over k). thread: 2 i x 4 j ----
    {
        const int i0 = w * 4 + half * 2;
        u64 aA[2][4];
#pragma unroll
        for (int r = 0; r < 2; r++)
#pragma unroll
            for (int s = 0; s < 4; s++) aA[r][s] = 0ull;

#pragma unroll
        for (int kp = 0; kp < DK / 2; kp++) {
            u64 a0 = lds64(&sQ[(i0    ) * PK + 2 * kp]);
            u64 a1 = lds64(&sQ[(i0 + 1) * PK + 2 * kp]);
            u64 bb[4];
#pragma unroll
            for (int s = 0; s < 4; s++) bb[s] = lds64(&sK[(txl + 16 * s) * PK + 2 * kp]);
#pragma unroll
            for (int s = 0; s < 4; s++) { fma2(aA[0][s], a0, bb[s]); fma2(aA[1][s], a1, bb[s]); }
        }
#pragma unroll
        for (int r = 0; r < 2; r++)
#pragma unroll
            for (int s = 0; s < 4; s++) {
                const int i = i0 + r, j = txl + 16 * s;
                float2 v = up2(aA[r][s]);
                sA[i * PJ + j] = (i >= j) ? (v.x + v.y) : 0.f;
            }
    }
    __syncthreads();

    // ---- Z: rowsum(A) + phiQ . Kspre ----
    {
        const int iz = tid & 63, p = tid >> 6;
        float zp = 0.f;
#pragma unroll
        for (int j = p * 8; j < p * 8 + 8; j++) zp += sA[iz * PJ + j];
#pragma unroll
        for (int k = p * 16; k < p * 16 + 16; k++) zp += sQ[iz * PK + k] * sKs[k];
        atomicAdd(&sZ[iz], zp);
    }

    // ---- phase 2: out = A V + phiQ Spre. thread: 4 i x 4 v, v-packed mixed ----
    const int i0 = w * 4;          // 16 warps x 4 = 64 rows (warp-uniform)
    const int v0 = tx * 4;         // 32 lanes x 4 = 128 cols

    u64   c2[2][2];   // FMA2 accs for i0, i0+1 : [(v0,v0+1), (v0+2,v0+3)]
    float cs[2][4];   // scalar accs for i0+2, i0+3
#pragma unroll
    for (int r = 0; r < 2; r++) {
        c2[r][0] = c2[r][1] = 0ull;
#pragma unroll
        for (int s = 0; s < 4; s++) cs[r][s] = 0.f;
    }

#pragma unroll 4
    for (int j = 0; j < C; j++) {          // intra-chunk: b from sV rows
        const float a0 = sA[(i0    ) * PJ + j];
        const float a1 = sA[(i0 + 1) * PJ + j];
        const float a2v = sA[(i0 + 2) * PJ + j];
        const float a3v = sA[(i0 + 3) * PJ + j];
        const float4 F = *(const float4*)&sV[j * DV + v0];
        const u64 pA = pk(F.x, F.y), pB = pk(F.z, F.w);
        const u64 d0 = dup2(a0), d1 = dup2(a1);
        fma2(c2[0][0], d0, pA); fma2(c2[0][1], d0, pB);
        fma2(c2[1][0], d1, pA); fma2(c2[1][1], d1, pB);
        cs[0][0] = fmaf(a2v, F.x, cs[0][0]); cs[0][1] = fmaf(a2v, F.y, cs[0][1]);
        cs[0][2] = fmaf(a2v, F.z, cs[0][2]); cs[0][3] = fmaf(a2v, F.w, cs[0][3]);
        cs[1][0] = fmaf(a3v, F.x, cs[1][0]); cs[1][1] = fmaf(a3v, F.y, cs[1][1]);
        cs[1][2] = fmaf(a3v, F.z, cs[1][2]); cs[1][3] = fmaf(a3v, F.w, cs[1][3]);
    }

    const float* Sp = g_kvpre + (size_t)bc * DK * DV;   // [k][v], L1/L2 resident
#pragma unroll 4
    for (int k = 0; k < DK; k++) {         // inter-chunk
        const float a0 = sQ[(i0    ) * PK + k];
        const float a1 = sQ[(i0 + 1) * PK + k];
        const float a2v = sQ[(i0 + 2) * PK + k];
        const float a3v = sQ[(i0 + 3) * PK + k];
        const float4 F = __ldg((const float4*)&Sp[(size_t)k * DV + v0]);
        const u64 pA = pk(F.x, F.y), pB = pk(F.z, F.w);
        const u64 d0 = dup2(a0), d1 = dup2(a1);
        fma2(c2[0][0], d0, pA); fma2(c2[0][1], d0, pB);
        fma2(c2[1][0], d1, pA); fma2(c2[1][1], d1, pB);
        cs[0][0] = fmaf(a2v, F.x, cs[0][0]); cs[0][1] = fmaf(a2v, F.y, cs[0][1]);
        cs[0][2] = fmaf(a2v, F.z, cs[0][2]); cs[0][3] = fmaf(a2v, F.w, cs[0][3]);
        cs[1][0] = fmaf(a3v, F.x, cs[1][0]); cs[1][1] = fmaf(a3v, F.y, cs[1][1]);
        cs[1][2] = fmaf(a3v, F.z, cs[1][2]); cs[1][3] = fmaf(a3v, F.w, cs[1][3]);
    }

    __syncthreads();   // sZ complete

    // epilogue
#pragma unroll
    for (int r = 0; r < 2; r++) {
        const int i = i0 + r;
        const float invz = 1.f / (sZ[i] + EPS);
        float2 pa = up2(c2[r][0]), pb = up2(c2[r][1]);
        *(float4*)&out[((size_t)(b * Lc + l0 + i)) * DV + v0] =
            make_float4(pa.x * invz, pa.y * invz, pb.x * invz, pb.y * invz);
    }
#pragma unroll
    for (int r = 0; r < 2; r++) {
        const int i = i0 + 2 + r;
        const float invz = 1.f / (sZ[i] + EPS);
        *(float4*)&out[((size_t)(b * Lc + l0 + i)) * DV + v0] =
            make_float4(cs[r][0] * invz, cs[r][1] * invz, cs[r][2] * invz, cs[r][3] * invz);
    }
}

// ---------------------------------------------------------------------------
extern "C" void kernel_launch(void* const* d_in, const int* in_sizes, int n_in,
                              void* d_out, int out_size) {
    const float* Q = (const float*)d_in[0];
    const float* K = (const float*)d_in[1];
    const float* V = (const float*)d_in[2];
    float* out = (float*)d_out;

    const int smem3 = (2 * C * PK + C * PJ + C * DV + DK + C) * (int)sizeof(float); // ~117 KB
    cudaFuncSetAttribute(k_output, cudaFuncAttributeMaxDynamicSharedMemorySize, smem3);

    k_chunk_kv<<<2 * TC, 512>>>(K, V);
    k_scan<<<17, 512>>>();
    k_output<<<TC, 512, smem3>>>(Q, K, V, out);
}